// round 1
// baseline (speedup 1.0000x reference)
#include <cuda_runtime.h>
#include <math.h>

// Problem constants
#define BB   2
#define LL   2048
#define DM   1024
#define HH   16
#define DKK  64
#define MTOT (BB * LL)        // 4096

// Scratch: head-split [B,H,L,64] buffers (16 MB each)
__device__ float g_q[BB * HH * LL * DKK];
__device__ float g_k[BB * HH * LL * DKK];
__device__ float g_v[BB * HH * LL * DKK];
__device__ float g_o[BB * HH * LL * DKK];

// ---------------------------------------------------------------------------
// SGEMM: out[m,n] = sum_k A[m,k] * W[n,k] + bias[n]
// A is [4096,1024]; W is [1024,1024] stored [out,in] (torch Linear).
// a_headmerge: A[m,k] read from g_o head-split layout (k = h*64+d)
// o_headsplit: out written to head-split layout (n = h*64+d)
// Tile: BM=128, BN=64, BK=16; 256 threads; 8x4 micro-tile per thread.
// ---------------------------------------------------------------------------
__global__ void __launch_bounds__(256)
gemm_kernel(const float* __restrict__ A, const float* __restrict__ W,
            const float* __restrict__ bias, float* __restrict__ out,
            int a_headmerge, int o_headsplit)
{
    __shared__ float As[16][129];   // [k][m], padded
    __shared__ float Bs[16][65];    // [k][n], padded

    const int tid = threadIdx.x;
    const int tx = tid & 15;        // 0..15 -> 4 n-cols each
    const int ty = tid >> 4;        // 0..15 -> 8 m-rows each
    const int m0 = blockIdx.y * 128;
    const int n0 = blockIdx.x * 64;

    float acc[8][4];
#pragma unroll
    for (int i = 0; i < 8; i++)
#pragma unroll
        for (int j = 0; j < 4; j++) acc[i][j] = 0.f;

    for (int k0 = 0; k0 < DM; k0 += 16) {
        // Load A tile 128x16 (512 float4, 2 per thread), store transposed
#pragma unroll
        for (int t = 0; t < 2; t++) {
            int i = tid + t * 256;      // 0..511
            int row = i >> 2;           // 0..127
            int c4 = i & 3;             // 0..3
            int m = m0 + row;
            int k = k0 + c4 * 4;
            float4 val;
            if (!a_headmerge) {
                val = *reinterpret_cast<const float4*>(A + (size_t)m * DM + k);
            } else {
                int b = m / LL, l = m % LL;
                int h = k >> 6, d = k & 63;
                val = *reinterpret_cast<const float4*>(
                    A + (((size_t)(b * HH + h) * LL + l) << 6) + d);
            }
            As[c4 * 4 + 0][row] = val.x;
            As[c4 * 4 + 1][row] = val.y;
            As[c4 * 4 + 2][row] = val.z;
            As[c4 * 4 + 3][row] = val.w;
        }
        // Load W tile 64x16 (256 float4, 1 per thread), store transposed
        {
            int row = tid >> 2;         // 0..63
            int c4 = tid & 3;
            float4 val = *reinterpret_cast<const float4*>(
                W + (size_t)(n0 + row) * DM + k0 + c4 * 4);
            Bs[c4 * 4 + 0][row] = val.x;
            Bs[c4 * 4 + 1][row] = val.y;
            Bs[c4 * 4 + 2][row] = val.z;
            Bs[c4 * 4 + 3][row] = val.w;
        }
        __syncthreads();

#pragma unroll
        for (int kk = 0; kk < 16; kk++) {
            float a[8], b[4];
#pragma unroll
            for (int i = 0; i < 8; i++) a[i] = As[kk][ty * 8 + i];
#pragma unroll
            for (int j = 0; j < 4; j++) b[j] = Bs[kk][tx * 4 + j];
#pragma unroll
            for (int i = 0; i < 8; i++)
#pragma unroll
                for (int j = 0; j < 4; j++) acc[i][j] += a[i] * b[j];
        }
        __syncthreads();
    }

    // Epilogue
    const int n = n0 + tx * 4;
    float4 bv = *reinterpret_cast<const float4*>(bias + n);
#pragma unroll
    for (int i = 0; i < 8; i++) {
        int m = m0 + ty * 8 + i;
        float4 o;
        o.x = acc[i][0] + bv.x;
        o.y = acc[i][1] + bv.y;
        o.z = acc[i][2] + bv.z;
        o.w = acc[i][3] + bv.w;
        if (o_headsplit) {
            int b = m / LL, l = m % LL;
            int h = n >> 6, d = n & 63;
            *reinterpret_cast<float4*>(
                out + (((size_t)(b * HH + h) * LL + l) << 6) + d) = o;
        } else {
            *reinterpret_cast<float4*>(out + (size_t)m * DM + n) = o;
        }
    }
}

// ---------------------------------------------------------------------------
// Causal flash attention, d_k = 64.
// Grid: (L/64, B*H). Block: 256 threads.
// Thread (r = tid>>2, c = tid&3): query row r, 16 contiguous cols c*16..c*16+15.
// smem stride 68 floats: float4-aligned + bank rotation.
// ---------------------------------------------------------------------------
#define ASTRIDE 68
#define SMEM_ATTN (4 * 64 * ASTRIDE * 4)   // 69632 bytes

__global__ void __launch_bounds__(256)
attn_kernel()
{
    extern __shared__ float sm[];
    float (*Qs)[ASTRIDE] = (float(*)[ASTRIDE])(sm);
    float (*Kt)[ASTRIDE] = (float(*)[ASTRIDE])(sm + 64 * ASTRIDE);      // [d][j]
    float (*Vs)[ASTRIDE] = (float(*)[ASTRIDE])(sm + 2 * 64 * ASTRIDE); // [j][d]
    float (*Ps)[ASTRIDE] = (float(*)[ASTRIDE])(sm + 3 * 64 * ASTRIDE); // [r][j]

    const int tid = threadIdx.x;
    const int r = tid >> 2;
    const int c = tid & 3;
    const int qb = blockIdx.x;
    const int bh = blockIdx.y;
    const size_t base = (size_t)bh * LL * DKK;
    const int qg = qb * 64 + r;

    // Load Q tile (64x64), float4 stores
#pragma unroll
    for (int t = 0; t < 4; t++) {
        int i = tid + t * 256;       // 0..1023 float4s
        int row = i >> 4;            // 0..63
        int c4 = i & 15;             // 0..15
        float4 v = *reinterpret_cast<const float4*>(
            g_q + base + ((size_t)(qb * 64 + row) << 6) + c4 * 4);
        *reinterpret_cast<float4*>(&Qs[row][c4 * 4]) = v;
    }

    float acc[16];
#pragma unroll
    for (int i = 0; i < 16; i++) acc[i] = 0.f;
    float mrow = -1e30f, lrow = 0.f;

    for (int kt = 0; kt <= qb; kt++) {
        __syncthreads();   // protect Kt/Vs from previous tile's readers
        // Load K (transposed -> Kt[d][j]) and V (Vs[j][d])
#pragma unroll
        for (int t = 0; t < 4; t++) {
            int i = tid + t * 256;
            int row = i >> 4;
            int c4 = i & 15;
            size_t goff = base + ((size_t)(kt * 64 + row) << 6) + c4 * 4;
            float4 kv = *reinterpret_cast<const float4*>(g_k + goff);
            Kt[c4 * 4 + 0][row] = kv.x;
            Kt[c4 * 4 + 1][row] = kv.y;
            Kt[c4 * 4 + 2][row] = kv.z;
            Kt[c4 * 4 + 3][row] = kv.w;
            float4 vv = *reinterpret_cast<const float4*>(g_v + goff);
            *reinterpret_cast<float4*>(&Vs[row][c4 * 4]) = vv;
        }
        __syncthreads();

        // S = Q @ K^T for this thread's 16 key cols
        float s[16];
#pragma unroll
        for (int j = 0; j < 16; j++) s[j] = 0.f;
#pragma unroll 8
        for (int d = 0; d < 64; d++) {
            float qv = Qs[r][d];
#pragma unroll
            for (int q4 = 0; q4 < 4; q4++) {
                float4 kv = *reinterpret_cast<const float4*>(&Kt[d][c * 16 + q4 * 4]);
                s[q4 * 4 + 0] += qv * kv.x;
                s[q4 * 4 + 1] += qv * kv.y;
                s[q4 * 4 + 2] += qv * kv.z;
                s[q4 * 4 + 3] += qv * kv.w;
            }
        }

        const bool diag = (kt == qb);
        float tmax = -1e30f;
#pragma unroll
        for (int j = 0; j < 16; j++) {
            s[j] *= 0.125f;   // 1/sqrt(64)
            if (diag && (kt * 64 + c * 16 + j) > qg) s[j] = -1e30f;
            tmax = fmaxf(tmax, s[j]);
        }
        tmax = fmaxf(tmax, __shfl_xor_sync(0xffffffffu, tmax, 1));
        tmax = fmaxf(tmax, __shfl_xor_sync(0xffffffffu, tmax, 2));

        float mnew = fmaxf(mrow, tmax);
        float corr = __expf(mrow - mnew);
        float rsum = 0.f;
#pragma unroll
        for (int j = 0; j < 16; j++) {
            float p = __expf(s[j] - mnew);
            Ps[r][c * 16 + j] = p;
            rsum += p;
        }
        rsum += __shfl_xor_sync(0xffffffffu, rsum, 1);
        rsum += __shfl_xor_sync(0xffffffffu, rsum, 2);
        lrow = lrow * corr + rsum;
        mrow = mnew;
#pragma unroll
        for (int i = 0; i < 16; i++) acc[i] *= corr;

        __syncwarp();   // Ps row shared only within warp (lanes 4r..4r+3)

        // acc += P @ V for this thread's 16 d-cols
#pragma unroll 8
        for (int j = 0; j < 64; j++) {
            float pj = Ps[r][j];
#pragma unroll
            for (int q4 = 0; q4 < 4; q4++) {
                float4 vv = *reinterpret_cast<const float4*>(&Vs[j][c * 16 + q4 * 4]);
                acc[q4 * 4 + 0] += pj * vv.x;
                acc[q4 * 4 + 1] += pj * vv.y;
                acc[q4 * 4 + 2] += pj * vv.z;
                acc[q4 * 4 + 3] += pj * vv.w;
            }
        }
    }

    const float inv = 1.0f / lrow;
    float* optr = g_o + base + ((size_t)qg << 6) + c * 16;
#pragma unroll
    for (int q4 = 0; q4 < 4; q4++) {
        float4 o;
        o.x = acc[q4 * 4 + 0] * inv;
        o.y = acc[q4 * 4 + 1] * inv;
        o.z = acc[q4 * 4 + 2] * inv;
        o.w = acc[q4 * 4 + 3] * inv;
        *reinterpret_cast<float4*>(optr + q4 * 4) = o;
    }
}

// ---------------------------------------------------------------------------
// Launch
// ---------------------------------------------------------------------------
extern "C" void kernel_launch(void* const* d_in, const int* in_sizes, int n_in,
                              void* d_out, int out_size)
{
    const float* Q  = (const float*)d_in[0];
    const float* K  = (const float*)d_in[1];
    const float* V  = (const float*)d_in[2];
    // d_in[3] = mask (causal, known statically; unused)
    const float* Wq = (const float*)d_in[4];
    const float* bq = (const float*)d_in[5];
    const float* Wk = (const float*)d_in[6];
    const float* bk = (const float*)d_in[7];
    const float* Wv = (const float*)d_in[8];
    const float* bv = (const float*)d_in[9];
    const float* Wo = (const float*)d_in[10];
    const float* bo = (const float*)d_in[11];
    float* out = (float*)d_out;

    float *gq, *gk, *gv, *go;
    cudaGetSymbolAddress((void**)&gq, g_q);
    cudaGetSymbolAddress((void**)&gk, g_k);
    cudaGetSymbolAddress((void**)&gv, g_v);
    cudaGetSymbolAddress((void**)&go, g_o);

    cudaFuncSetAttribute(attn_kernel,
                         cudaFuncAttributeMaxDynamicSharedMemorySize, SMEM_ATTN);

    dim3 ggrid(DM / 64, MTOT / 128);   // (16, 32)

    gemm_kernel<<<ggrid, 256>>>(Q, Wq, bq, gq, 0, 1);
    gemm_kernel<<<ggrid, 256>>>(K, Wk, bk, gk, 0, 1);
    gemm_kernel<<<ggrid, 256>>>(V, Wv, bv, gv, 0, 1);

    attn_kernel<<<dim3(LL / 64, BB * HH), 256, SMEM_ATTN>>>();

    gemm_kernel<<<ggrid, 256>>>(go, Wo, bo, out, 1, 0);
}

// round 4
// speedup vs baseline: 1.2152x; 1.2152x over previous
#include <cuda_runtime.h>
#include <cstdint>
#include <math.h>

// Problem constants
#define BB   2
#define LL   2048
#define DM   1024
#define HH   16
#define MTOT (BB * LL)        // 4096

// Scratch buffers
__device__ float g_q[MTOT * DM];   // head-split [B,H,L,64]
__device__ float g_k[MTOT * DM];
__device__ float g_v[MTOT * DM];
__device__ float g_o[MTOT * DM];   // merged [B,L,D]

// ---------------------------------------------------------------------------
// helpers
// ---------------------------------------------------------------------------
__device__ __forceinline__ uint32_t smem_u32(const void* p) {
    uint32_t a;
    asm("{ .reg .u64 t; cvta.to.shared.u64 t, %1; cvt.u32.u64 %0, t; }"
        : "=r"(a) : "l"(p));
    return a;
}

#define LDSM4(r0, r1, r2, r3, addr)                                            \
    asm volatile("ldmatrix.sync.aligned.m8n8.x4.shared.b16 {%0,%1,%2,%3}, [%4];" \
                 : "=r"(r0), "=r"(r1), "=r"(r2), "=r"(r3) : "r"(addr))

#define MMA_TF32(d, a, b)                                                      \
    asm volatile("mma.sync.aligned.m16n8k8.row.col.f32.tf32.tf32.f32 "         \
                 "{%0,%1,%2,%3},{%4,%5,%6,%7},{%8,%9},{%0,%1,%2,%3};"          \
                 : "+f"((d)[0]), "+f"((d)[1]), "+f"((d)[2]), "+f"((d)[3])      \
                 : "r"((a)[0]), "r"((a)[1]), "r"((a)[2]), "r"((a)[3]),         \
                   "r"((b)[0]), "r"((b)[1]))

// ---------------------------------------------------------------------------
// tf32 mma.sync GEMM: out[m,n] = sum_k A[m,k]*W[n,k] + bias[n]
// BM=BN=128, BK=32; 256 threads (8 warps, 2x4 grid, 64x32 warp tile).
// Double-buffered smem, register-staged global loads with RN-tf32 rounding
// (+0x1000 on the f32 bit pattern; HW truncation then = round-to-nearest).
// SW128 swizzle: off = row*128 + ((c16 ^ (row&7))<<4) — conflict-free STS.128
// and ldmatrix.
// ---------------------------------------------------------------------------
#define BM 128
#define BN 128
#define BK 32
#define NCH (DM / BK)            // 32
#define STAGE_A (BM * BK * 4)    // 16384 B
#define STAGE_B (BN * BK * 4)    // 16384 B
#define GEMM_SMEM (2 * (STAGE_A + STAGE_B))   // 65536 B

__global__ void __launch_bounds__(256, 1)
gemm_mma(const float* __restrict__ A, const float* __restrict__ W,
         const float* __restrict__ bias, float* __restrict__ out,
         int o_headsplit)
{
    extern __shared__ char sm[];
    const uint32_t smA = smem_u32(sm);
    const uint32_t smB = smA + 2 * STAGE_A;

    const int tid  = threadIdx.x;
    const int lane = tid & 31;
    const int wid  = tid >> 5;
    const int wm   = (wid & 1) * 64;    // warp m-offset
    const int wn   = (wid >> 1) * 32;   // warp n-offset
    const int m0 = blockIdx.y * BM;
    const int n0 = blockIdx.x * BN;

    const float* Aptr = A + (size_t)m0 * DM;
    const float* Wptr = W + (size_t)n0 * DM;

    // ldmatrix per-thread geometry
    const int tArow = wm + ((lane >> 3) & 1) * 8 + (lane & 7);  // + mi*16
    const int tAc   = lane >> 4;                                // k half (0/1)
    const int tBrow = wn + ((lane >> 4) & 1) * 8 + (lane & 7);  // + j*16
    const int tBc   = (lane >> 3) & 1;

    float acc[4][4][4];
#pragma unroll
    for (int i = 0; i < 4; i++)
#pragma unroll
        for (int j = 0; j < 4; j++)
#pragma unroll
            for (int k = 0; k < 4; k++) acc[i][j][k] = 0.f;

    uint4 ra[4], rb[4];

#define LDG_CH(c) do {                                                         \
    _Pragma("unroll")                                                          \
    for (int j = 0; j < 4; j++) {                                              \
        const int i = tid + j * 256;                                           \
        const int row = i >> 3, c4 = i & 7;                                    \
        ra[j] = *(const uint4*)(Aptr + (size_t)row * DM + (c) * BK + c4 * 4);  \
        rb[j] = *(const uint4*)(Wptr + (size_t)row * DM + (c) * BK + c4 * 4);  \
    }                                                                          \
} while (0)

#define STS_CH(s) do {                                                         \
    _Pragma("unroll")                                                          \
    for (int j = 0; j < 4; j++) {                                              \
        const int i = tid + j * 256;                                           \
        const int row = i >> 3, c4 = i & 7;                                    \
        const uint32_t off = row * 128 + (((c4) ^ (row & 7)) << 4);            \
        uint4 va = ra[j];                                                      \
        va.x += 0x1000u; va.y += 0x1000u; va.z += 0x1000u; va.w += 0x1000u;    \
        *(uint4*)(sm + (s) * STAGE_A + off) = va;                              \
        uint4 vb = rb[j];                                                      \
        vb.x += 0x1000u; vb.y += 0x1000u; vb.z += 0x1000u; vb.w += 0x1000u;    \
        *(uint4*)(sm + 2 * STAGE_A + (s) * STAGE_B + off) = vb;                \
    }                                                                          \
} while (0)

    // prologue
    LDG_CH(0);
    STS_CH(0);
    LDG_CH(1);
    __syncthreads();

    for (int c = 0; c < NCH; ++c) {
        const int s = c & 1;
        if (c + 1 < NCH) STS_CH((c + 1) & 1);
        if (c + 2 < NCH) LDG_CH(c + 2);

        const uint32_t aBase = smA + s * STAGE_A;
        const uint32_t bBase = smB + s * STAGE_B;
#pragma unroll
        for (int ks = 0; ks < 4; ks++) {
            uint32_t a[4][4], b[2][4];
#pragma unroll
            for (int mi = 0; mi < 4; mi++) {
                const int row = tArow + mi * 16;
                const int cc = ks * 2 + tAc;
                const uint32_t addr = aBase + row * 128 + ((cc ^ (row & 7)) << 4);
                LDSM4(a[mi][0], a[mi][1], a[mi][2], a[mi][3], addr);
            }
#pragma unroll
            for (int j = 0; j < 2; j++) {
                const int row = tBrow + j * 16;
                const int cc = ks * 2 + tBc;
                const uint32_t addr = bBase + row * 128 + ((cc ^ (row & 7)) << 4);
                LDSM4(b[j][0], b[j][1], b[j][2], b[j][3], addr);
            }
#pragma unroll
            for (int mi = 0; mi < 4; mi++) {
                MMA_TF32(acc[mi][0], a[mi], b[0]);
                MMA_TF32(acc[mi][1], a[mi], b[0] + 2);
                MMA_TF32(acc[mi][2], a[mi], b[1]);
                MMA_TF32(acc[mi][3], a[mi], b[1] + 2);
            }
        }
        __syncthreads();
    }

    // epilogue: bias + store (float2 per row-half)
    const int r0q = lane >> 2;          // 0..7
    const int c0q = (lane & 3) * 2;     // 0,2,4,6
#pragma unroll
    for (int mi = 0; mi < 4; mi++) {
#pragma unroll
        for (int ni = 0; ni < 4; ni++) {
            const int n = n0 + wn + ni * 8 + c0q;
            const float2 b2 = *(const float2*)(bias + n);
#pragma unroll
            for (int h = 0; h < 2; h++) {
                const int m = m0 + wm + mi * 16 + r0q + h * 8;
                float2 v;
                v.x = acc[mi][ni][h * 2 + 0] + b2.x;
                v.y = acc[mi][ni][h * 2 + 1] + b2.y;
                if (o_headsplit) {
                    const int bb = m >> 11, l = m & 2047;
                    const int hh = n >> 6, d = n & 63;
                    *(float2*)(out + (((size_t)(bb * HH + hh) * LL + l) << 6) + d) = v;
                } else {
                    *(float2*)(out + (size_t)m * DM + n) = v;
                }
            }
        }
    }
#undef LDG_CH
#undef STS_CH
}

// ---------------------------------------------------------------------------
// Causal flash attention, d_k = 64 (fp32 SIMT).
// Grid: (L/64, B*H). Block: 256 threads. Output merged [B,L,D].
// ---------------------------------------------------------------------------
#define ASTRIDE 68
#define SMEM_ATTN (4 * 64 * ASTRIDE * 4)   // 69632 bytes

__global__ void __launch_bounds__(256)
attn_kernel()
{
    extern __shared__ float smf[];
    float (*Qs)[ASTRIDE] = (float(*)[ASTRIDE])(smf);
    float (*Kt)[ASTRIDE] = (float(*)[ASTRIDE])(smf + 64 * ASTRIDE);
    float (*Vs)[ASTRIDE] = (float(*)[ASTRIDE])(smf + 2 * 64 * ASTRIDE);
    float (*Ps)[ASTRIDE] = (float(*)[ASTRIDE])(smf + 3 * 64 * ASTRIDE);

    const int tid = threadIdx.x;
    const int r = tid >> 2;
    const int c = tid & 3;
    const int qb = blockIdx.x;
    const int bh = blockIdx.y;
    const size_t base = (size_t)bh * LL * 64;
    const int qg = qb * 64 + r;

#pragma unroll
    for (int t = 0; t < 4; t++) {
        int i = tid + t * 256;
        int row = i >> 4;
        int c4 = i & 15;
        float4 v = *reinterpret_cast<const float4*>(
            g_q + base + ((size_t)(qb * 64 + row) << 6) + c4 * 4);
        *reinterpret_cast<float4*>(&Qs[row][c4 * 4]) = v;
    }

    float acc[16];
#pragma unroll
    for (int i = 0; i < 16; i++) acc[i] = 0.f;
    float mrow = -1e30f, lrow = 0.f;

    for (int kt = 0; kt <= qb; kt++) {
        __syncthreads();
#pragma unroll
        for (int t = 0; t < 4; t++) {
            int i = tid + t * 256;
            int row = i >> 4;
            int c4 = i & 15;
            size_t goff = base + ((size_t)(kt * 64 + row) << 6) + c4 * 4;
            float4 kv = *reinterpret_cast<const float4*>(g_k + goff);
            Kt[c4 * 4 + 0][row] = kv.x;
            Kt[c4 * 4 + 1][row] = kv.y;
            Kt[c4 * 4 + 2][row] = kv.z;
            Kt[c4 * 4 + 3][row] = kv.w;
            float4 vv = *reinterpret_cast<const float4*>(g_v + goff);
            *reinterpret_cast<float4*>(&Vs[row][c4 * 4]) = vv;
        }
        __syncthreads();

        float s[16];
#pragma unroll
        for (int j = 0; j < 16; j++) s[j] = 0.f;
#pragma unroll 8
        for (int d = 0; d < 64; d++) {
            float qv = Qs[r][d];
#pragma unroll
            for (int q4 = 0; q4 < 4; q4++) {
                float4 kv = *reinterpret_cast<const float4*>(&Kt[d][c * 16 + q4 * 4]);
                s[q4 * 4 + 0] += qv * kv.x;
                s[q4 * 4 + 1] += qv * kv.y;
                s[q4 * 4 + 2] += qv * kv.z;
                s[q4 * 4 + 3] += qv * kv.w;
            }
        }

        const bool diag = (kt == qb);
        float tmax = -1e30f;
#pragma unroll
        for (int j = 0; j < 16; j++) {
            s[j] *= 0.125f;
            if (diag && (kt * 64 + c * 16 + j) > qg) s[j] = -1e30f;
            tmax = fmaxf(tmax, s[j]);
        }
        tmax = fmaxf(tmax, __shfl_xor_sync(0xffffffffu, tmax, 1));
        tmax = fmaxf(tmax, __shfl_xor_sync(0xffffffffu, tmax, 2));

        float mnew = fmaxf(mrow, tmax);
        float corr = __expf(mrow - mnew);
        float rsum = 0.f;
#pragma unroll
        for (int j = 0; j < 16; j++) {
            float p = __expf(s[j] - mnew);
            Ps[r][c * 16 + j] = p;
            rsum += p;
        }
        rsum += __shfl_xor_sync(0xffffffffu, rsum, 1);
        rsum += __shfl_xor_sync(0xffffffffu, rsum, 2);
        lrow = lrow * corr + rsum;
        mrow = mnew;
#pragma unroll
        for (int i = 0; i < 16; i++) acc[i] *= corr;

        __syncwarp();

#pragma unroll 8
        for (int j = 0; j < 64; j++) {
            float pj = Ps[r][j];
#pragma unroll
            for (int q4 = 0; q4 < 4; q4++) {
                float4 vv = *reinterpret_cast<const float4*>(&Vs[j][c * 16 + q4 * 4]);
                acc[q4 * 4 + 0] += pj * vv.x;
                acc[q4 * 4 + 1] += pj * vv.y;
                acc[q4 * 4 + 2] += pj * vv.z;
                acc[q4 * 4 + 3] += pj * vv.w;
            }
        }
    }

    const float inv = 1.0f / lrow;
    const int b = bh >> 4, h = bh & 15;
    float* optr = g_o + ((size_t)(b * LL + qg)) * DM + h * 64 + c * 16;
#pragma unroll
    for (int q4 = 0; q4 < 4; q4++) {
        float4 o;
        o.x = acc[q4 * 4 + 0] * inv;
        o.y = acc[q4 * 4 + 1] * inv;
        o.z = acc[q4 * 4 + 2] * inv;
        o.w = acc[q4 * 4 + 3] * inv;
        *reinterpret_cast<float4*>(optr + q4 * 4) = o;
    }
}

// ---------------------------------------------------------------------------
// Launch
// ---------------------------------------------------------------------------
extern "C" void kernel_launch(void* const* d_in, const int* in_sizes, int n_in,
                              void* d_out, int out_size)
{
    const float* Q  = (const float*)d_in[0];
    const float* K  = (const float*)d_in[1];
    const float* V  = (const float*)d_in[2];
    const float* Wq = (const float*)d_in[4];
    const float* bq = (const float*)d_in[5];
    const float* Wk = (const float*)d_in[6];
    const float* bk = (const float*)d_in[7];
    const float* Wv = (const float*)d_in[8];
    const float* bv = (const float*)d_in[9];
    const float* Wo = (const float*)d_in[10];
    const float* bo = (const float*)d_in[11];
    float* out = (float*)d_out;

    float *gq, *gk, *gv, *go;
    cudaGetSymbolAddress((void**)&gq, g_q);
    cudaGetSymbolAddress((void**)&gk, g_k);
    cudaGetSymbolAddress((void**)&gv, g_v);
    cudaGetSymbolAddress((void**)&go, g_o);

    cudaFuncSetAttribute(gemm_mma,
                         cudaFuncAttributeMaxDynamicSharedMemorySize, GEMM_SMEM);
    cudaFuncSetAttribute(attn_kernel,
                         cudaFuncAttributeMaxDynamicSharedMemorySize, SMEM_ATTN);

    dim3 ggrid(DM / BN, MTOT / BM);   // (8, 32)

    gemm_mma<<<ggrid, 256, GEMM_SMEM>>>(Q, Wq, bq, gq, 1);
    gemm_mma<<<ggrid, 256, GEMM_SMEM>>>(K, Wk, bk, gk, 1);
    gemm_mma<<<ggrid, 256, GEMM_SMEM>>>(V, Wv, bv, gv, 1);

    attn_kernel<<<dim3(LL / 64, BB * HH), 256, SMEM_ATTN>>>();

    gemm_mma<<<ggrid, 256, GEMM_SMEM>>>(go, Wo, bo, out, 0);
}

// round 6
// speedup vs baseline: 8.5181x; 7.0094x over previous
#include <cuda_runtime.h>
#include <cuda_fp16.h>
#include <cstdint>
#include <math.h>

// Problem constants
#define BB   2
#define LL   2048
#define DM   1024
#define HH   16
#define MTOT (BB * LL)        // 4096

// Scratch buffers
__device__ float  g_q[MTOT * DM];            // head-split [B,H,L,64] (+RN bias bits)
__device__ float  g_k[MTOT * DM];            // head-split [B,H,L,64] (+RN bias bits)
__device__ __half g_vT[(size_t)BB * HH * 64 * LL];  // transposed f16 [B,H,64,L]
__device__ float  g_o[MTOT * DM];            // merged [B,L,D]

// ---------------------------------------------------------------------------
// helpers
// ---------------------------------------------------------------------------
__device__ __forceinline__ uint32_t smem_u32(const void* p) {
    uint32_t a;
    asm("{ .reg .u64 t; cvta.to.shared.u64 t, %1; cvt.u32.u64 %0, t; }"
        : "=r"(a) : "l"(p));
    return a;
}

#define LDSM4(r0, r1, r2, r3, addr)                                            \
    asm volatile("ldmatrix.sync.aligned.m8n8.x4.shared.b16 {%0,%1,%2,%3}, [%4];" \
                 : "=r"(r0), "=r"(r1), "=r"(r2), "=r"(r3) : "r"(addr))

#define MMA_TF32(d, a, b)                                                      \
    asm volatile("mma.sync.aligned.m16n8k8.row.col.f32.tf32.tf32.f32 "         \
                 "{%0,%1,%2,%3},{%4,%5,%6,%7},{%8,%9},{%0,%1,%2,%3};"          \
                 : "+f"((d)[0]), "+f"((d)[1]), "+f"((d)[2]), "+f"((d)[3])      \
                 : "r"((a)[0]), "r"((a)[1]), "r"((a)[2]), "r"((a)[3]),         \
                   "r"((b)[0]), "r"((b)[1]))

#define MMA_F16(d, a, b)                                                       \
    asm volatile("mma.sync.aligned.m16n8k16.row.col.f32.f16.f16.f32 "          \
                 "{%0,%1,%2,%3},{%4,%5,%6,%7},{%8,%9},{%0,%1,%2,%3};"          \
                 : "+f"((d)[0]), "+f"((d)[1]), "+f"((d)[2]), "+f"((d)[3])      \
                 : "r"((a)[0]), "r"((a)[1]), "r"((a)[2]), "r"((a)[3]),         \
                   "r"((b)[0]), "r"((b)[1]))

#define CP_ASYNC16(dst, src) \
    asm volatile("cp.async.cg.shared.global [%0], [%1], 16;" :: "r"(dst), "l"(src) : "memory")
#define CP_COMMIT() asm volatile("cp.async.commit_group;" ::: "memory")
#define CP_WAIT(n)  asm volatile("cp.async.wait_group %0;" :: "n"(n) : "memory")

__device__ __forceinline__ uint32_t h2pack(float x, float y) {
    __half2 h = __floats2half2_rn(x, y);
    return *reinterpret_cast<uint32_t*>(&h);
}

// ---------------------------------------------------------------------------
// tf32 mma.sync GEMM: out[m,n] = sum_k A[m,k]*W[n,k] + bias[n]
// BM=BN=128, BK=32; 256 threads (8 warps, 2x4, 64x32 warp tile).
// mode 0: plain f32 [m][n] out
// mode 1: head-split f32 [B,H,L,64] with +0x1000 RN-bias (tf32 consumer)
// mode 2: transposed f16 [B,H,64,L] (attention V operand)
// ---------------------------------------------------------------------------
#define BM 128
#define BN 128
#define BK 32
#define NCH (DM / BK)            // 32
#define STAGE_A (BM * BK * 4)    // 16384 B
#define STAGE_B (BN * BK * 4)    // 16384 B
#define GEMM_SMEM (2 * (STAGE_A + STAGE_B))   // 65536 B

__global__ void __launch_bounds__(256, 1)
gemm_mma(const float* __restrict__ A, const float* __restrict__ W,
         const float* __restrict__ bias, float* __restrict__ out,
         __half* __restrict__ outT, int mode)
{
    extern __shared__ char sm[];
    const uint32_t smA = smem_u32(sm);
    const uint32_t smB = smA + 2 * STAGE_A;

    const int tid  = threadIdx.x;
    const int lane = tid & 31;
    const int wid  = tid >> 5;
    const int wm   = (wid & 1) * 64;
    const int wn   = (wid >> 1) * 32;
    const int m0 = blockIdx.y * BM;
    const int n0 = blockIdx.x * BN;

    const float* Aptr = A + (size_t)m0 * DM;
    const float* Wptr = W + (size_t)n0 * DM;

    const int tArow = wm + ((lane >> 3) & 1) * 8 + (lane & 7);
    const int tAc   = lane >> 4;
    const int tBrow = wn + ((lane >> 4) & 1) * 8 + (lane & 7);
    const int tBc   = (lane >> 3) & 1;

    float acc[4][4][4];
#pragma unroll
    for (int i = 0; i < 4; i++)
#pragma unroll
        for (int j = 0; j < 4; j++)
#pragma unroll
            for (int k = 0; k < 4; k++) acc[i][j][k] = 0.f;

    uint4 ra[4], rb[4];

#define LDG_CH(c) do {                                                         \
    _Pragma("unroll")                                                          \
    for (int j = 0; j < 4; j++) {                                              \
        const int i = tid + j * 256;                                           \
        const int row = i >> 3, c4 = i & 7;                                    \
        ra[j] = *(const uint4*)(Aptr + (size_t)row * DM + (c) * BK + c4 * 4);  \
        rb[j] = *(const uint4*)(Wptr + (size_t)row * DM + (c) * BK + c4 * 4);  \
    }                                                                          \
} while (0)

#define STS_CH(s) do {                                                         \
    _Pragma("unroll")                                                          \
    for (int j = 0; j < 4; j++) {                                              \
        const int i = tid + j * 256;                                           \
        const int row = i >> 3, c4 = i & 7;                                    \
        const uint32_t off = row * 128 + (((c4) ^ (row & 7)) << 4);            \
        uint4 va = ra[j];                                                      \
        va.x += 0x1000u; va.y += 0x1000u; va.z += 0x1000u; va.w += 0x1000u;    \
        *(uint4*)(sm + (s) * STAGE_A + off) = va;                              \
        uint4 vb = rb[j];                                                      \
        vb.x += 0x1000u; vb.y += 0x1000u; vb.z += 0x1000u; vb.w += 0x1000u;    \
        *(uint4*)(sm + 2 * STAGE_A + (s) * STAGE_B + off) = vb;                \
    }                                                                          \
} while (0)

    LDG_CH(0);
    STS_CH(0);
    LDG_CH(1);
    __syncthreads();

    for (int c = 0; c < NCH; ++c) {
        const int s = c & 1;
        if (c + 1 < NCH) STS_CH((c + 1) & 1);
        if (c + 2 < NCH) LDG_CH(c + 2);

        const uint32_t aBase = smA + s * STAGE_A;
        const uint32_t bBase = smB + s * STAGE_B;
#pragma unroll
        for (int ks = 0; ks < 4; ks++) {
            uint32_t a[4][4], b[2][4];
#pragma unroll
            for (int mi = 0; mi < 4; mi++) {
                const int row = tArow + mi * 16;
                const int cc = ks * 2 + tAc;
                const uint32_t addr = aBase + row * 128 + ((cc ^ (row & 7)) << 4);
                LDSM4(a[mi][0], a[mi][1], a[mi][2], a[mi][3], addr);
            }
#pragma unroll
            for (int j = 0; j < 2; j++) {
                const int row = tBrow + j * 16;
                const int cc = ks * 2 + tBc;
                const uint32_t addr = bBase + row * 128 + ((cc ^ (row & 7)) << 4);
                LDSM4(b[j][0], b[j][1], b[j][2], b[j][3], addr);
            }
#pragma unroll
            for (int mi = 0; mi < 4; mi++) {
                MMA_TF32(acc[mi][0], a[mi], b[0]);
                MMA_TF32(acc[mi][1], a[mi], b[0] + 2);
                MMA_TF32(acc[mi][2], a[mi], b[1]);
                MMA_TF32(acc[mi][3], a[mi], b[1] + 2);
            }
        }
        __syncthreads();
    }

    const int r0q = lane >> 2;
    const int c0q = (lane & 3) * 2;
#pragma unroll
    for (int mi = 0; mi < 4; mi++) {
#pragma unroll
        for (int ni = 0; ni < 4; ni++) {
            const int n = n0 + wn + ni * 8 + c0q;
            const float2 b2 = *(const float2*)(bias + n);
#pragma unroll
            for (int h = 0; h < 2; h++) {
                const int m = m0 + wm + mi * 16 + r0q + h * 8;
                float2 v;
                v.x = acc[mi][ni][h * 2 + 0] + b2.x;
                v.y = acc[mi][ni][h * 2 + 1] + b2.y;
                if (mode == 1) {
                    const int bb = m >> 11, l = m & 2047;
                    const int hh = n >> 6, d = n & 63;
                    float2 vr;
                    vr.x = __uint_as_float(__float_as_uint(v.x) + 0x1000u);
                    vr.y = __uint_as_float(__float_as_uint(v.y) + 0x1000u);
                    *(float2*)(out + (((size_t)(bb * HH + hh) * LL + l) << 6) + d) = vr;
                } else if (mode == 2) {
                    const int bb = m >> 11, l = m & 2047;
                    const int hh = n >> 6, d = n & 63;
                    __half* p = outT + ((size_t)((bb * HH + hh) * 64 + d)) * LL + l;
                    p[0]  = __float2half_rn(v.x);
                    p[LL] = __float2half_rn(v.y);
                } else {
                    *(float2*)(out + (size_t)m * DM + n) = v;
                }
            }
        }
    }
#undef LDG_CH
#undef STS_CH
}

// ---------------------------------------------------------------------------
// Tensor-core causal flash attention, d_k = 64.
// Grid: (L/64, B*H). Block: 128 threads (4 warps, 16 q-rows each).
// QK^T: tf32 m16n8k8 (RN-biased operands). PV: f16 m16n8k16, P converted
// C-frag -> A-frag in registers; V pre-transposed f16 by the V projection.
// Double-buffered cp.async on K (f32, swizzled) and Vt (f16, swizzled).
// ---------------------------------------------------------------------------
#define AT_Q   0
#define AT_K   16384
#define AT_V   49152
#define AT_SMEM 65536

__global__ void __launch_bounds__(128)
attn_mma()
{
    extern __shared__ char sm[];
    const uint32_t sbase = smem_u32(sm);
    const uint32_t sQ = sbase + AT_Q;
    const uint32_t sK = sbase + AT_K;
    const uint32_t sV = sbase + AT_V;

    const int tid = threadIdx.x;
    const int lane = tid & 31;
    const int w = tid >> 5;
    const int qb = blockIdx.x;
    const int bh = blockIdx.y;
    const size_t gb = (size_t)bh * LL * 64;
    const __half* vtg = g_vT + (size_t)bh * 64 * LL;

#define LOAD_TILE(kt, buf) do {                                                \
    _Pragma("unroll")                                                          \
    for (int j = 0; j < 8; j++) {                                              \
        const int i = tid + j * 128;                                           \
        const int dh = i >> 9, r = (i >> 3) & 63, c4 = i & 7;                  \
        const float* src = g_k + gb + (size_t)((kt) * 64 + r) * 64 + dh * 32 + c4 * 4; \
        const uint32_t dst = sK + (buf) * 16384 + (dh * 64 + r) * 128          \
                           + ((c4 ^ (r & 7)) << 4);                            \
        CP_ASYNC16(dst, src);                                                  \
    }                                                                          \
    _Pragma("unroll")                                                          \
    for (int j = 0; j < 4; j++) {                                              \
        const int i = tid + j * 128;                                           \
        const int d = i >> 3, c = i & 7;                                       \
        const __half* src = vtg + (size_t)d * LL + (kt) * 64 + c * 8;          \
        const uint32_t dst = sV + (buf) * 8192 + d * 128 + ((c ^ (d & 7)) << 4); \
        CP_ASYNC16(dst, src);                                                  \
    }                                                                          \
} while (0)

    // Q tile -> smem (async)
#pragma unroll
    for (int j = 0; j < 8; j++) {
        const int i = tid + j * 128;
        const int dh = i >> 9, r = (i >> 3) & 63, c4 = i & 7;
        const float* src = g_q + gb + (size_t)(qb * 64 + r) * 64 + dh * 32 + c4 * 4;
        const uint32_t dst = sQ + (dh * 64 + r) * 128 + ((c4 ^ (r & 7)) << 4);
        CP_ASYNC16(dst, src);
    }
    CP_COMMIT();
    LOAD_TILE(0, 0);
    CP_COMMIT();
    CP_WAIT(1);          // Q ready
    __syncthreads();

    // Q fragments (32 regs)
    const int tArow = ((lane >> 3) & 1) * 8 + (lane & 7);
    const int tAc   = lane >> 4;
    const int qrow  = w * 16 + tArow;
    uint32_t qf[8][4];
#pragma unroll
    for (int ks = 0; ks < 8; ks++) {
        const int dh = ks >> 2;
        const int cc = (ks & 3) * 2 + tAc;
        const uint32_t addr = sQ + (dh * 64 + qrow) * 128 + ((cc ^ (qrow & 7)) << 4);
        LDSM4(qf[ks][0], qf[ks][1], qf[ks][2], qf[ks][3], addr);
    }

    float oacc[8][4];
#pragma unroll
    for (int i = 0; i < 8; i++)
#pragma unroll
        for (int j = 0; j < 4; j++) oacc[i][j] = 0.f;
    float mr0 = -1e30f, mr1 = -1e30f, lr0 = 0.f, lr1 = 0.f;

    const int tBrow = ((lane >> 4) & 1) * 8 + (lane & 7);
    const int tBc   = (lane >> 3) & 1;
    const int qg0 = qb * 64 + w * 16 + (lane >> 2);
    const int qg1 = qg0 + 8;
    const int vrr = (lane & 7) + ((lane >> 4) & 1) * 8;
    const int vkk = ((lane >> 3) & 1) * 8;

    for (int kt = 0; kt <= qb; kt++) {
        const int s = kt & 1;
        if (kt < qb) {
            LOAD_TILE(kt + 1, s ^ 1);
            CP_COMMIT();
            CP_WAIT(1);
        } else {
            CP_WAIT(0);
        }
        __syncthreads();

        // ---- S = Q K^T ----
        const uint32_t kb_ = sK + s * 16384;
        float sa[8][4];
#pragma unroll
        for (int i = 0; i < 8; i++)
#pragma unroll
            for (int j = 0; j < 4; j++) sa[i][j] = 0.f;
#pragma unroll
        for (int ks = 0; ks < 8; ks++) {
            const int dh = ks >> 2;
            const int cc = (ks & 3) * 2 + tBc;
#pragma unroll
            for (int n16 = 0; n16 < 4; n16++) {
                const int rr = n16 * 16 + tBrow;
                const uint32_t addr = kb_ + (dh * 64 + rr) * 128 + ((cc ^ (rr & 7)) << 4);
                uint32_t kb4[4];
                LDSM4(kb4[0], kb4[1], kb4[2], kb4[3], addr);
                MMA_TF32(sa[2 * n16 + 0], qf[ks], kb4);
                MMA_TF32(sa[2 * n16 + 1], qf[ks], kb4 + 2);
            }
        }

        // ---- mask + online softmax ----
        const bool diag = (kt == qb);
        const int colb = kt * 64 + 2 * (lane & 3);
        float tm0 = -1e30f, tm1 = -1e30f;
#pragma unroll
        for (int nt = 0; nt < 8; nt++) {
#pragma unroll
            for (int e = 0; e < 2; e++) {
                const int kg = colb + nt * 8 + e;
                float v0 = sa[nt][e] * 0.125f;
                if (diag && kg > qg0) v0 = -1e30f;
                sa[nt][e] = v0;
                tm0 = fmaxf(tm0, v0);
                float v1 = sa[nt][2 + e] * 0.125f;
                if (diag && kg > qg1) v1 = -1e30f;
                sa[nt][2 + e] = v1;
                tm1 = fmaxf(tm1, v1);
            }
        }
        tm0 = fmaxf(tm0, __shfl_xor_sync(0xffffffffu, tm0, 1));
        tm0 = fmaxf(tm0, __shfl_xor_sync(0xffffffffu, tm0, 2));
        tm1 = fmaxf(tm1, __shfl_xor_sync(0xffffffffu, tm1, 1));
        tm1 = fmaxf(tm1, __shfl_xor_sync(0xffffffffu, tm1, 2));

        const float mn0 = fmaxf(mr0, tm0);
        const float mn1 = fmaxf(mr1, tm1);
        const float corr0 = __expf(mr0 - mn0);
        const float corr1 = __expf(mr1 - mn1);
        float rs0 = 0.f, rs1 = 0.f;
#pragma unroll
        for (int nt = 0; nt < 8; nt++) {
#pragma unroll
            for (int e = 0; e < 2; e++) {
                const float p0 = __expf(sa[nt][e] - mn0);
                sa[nt][e] = p0; rs0 += p0;
                const float p1 = __expf(sa[nt][2 + e] - mn1);
                sa[nt][2 + e] = p1; rs1 += p1;
            }
        }
        rs0 += __shfl_xor_sync(0xffffffffu, rs0, 1);
        rs0 += __shfl_xor_sync(0xffffffffu, rs0, 2);
        rs1 += __shfl_xor_sync(0xffffffffu, rs1, 1);
        rs1 += __shfl_xor_sync(0xffffffffu, rs1, 2);
        lr0 = lr0 * corr0 + rs0;
        lr1 = lr1 * corr1 + rs1;
        mr0 = mn0; mr1 = mn1;
#pragma unroll
        for (int nt = 0; nt < 8; nt++) {
            oacc[nt][0] *= corr0; oacc[nt][1] *= corr0;
            oacc[nt][2] *= corr1; oacc[nt][3] *= corr1;
        }

        // ---- O += P V (f16) ----
        const uint32_t vb_ = sV + s * 8192;
#pragma unroll
        for (int kc = 0; kc < 4; kc++) {
            uint32_t pf[4];
            pf[0] = h2pack(sa[2 * kc][0],     sa[2 * kc][1]);
            pf[1] = h2pack(sa[2 * kc][2],     sa[2 * kc][3]);
            pf[2] = h2pack(sa[2 * kc + 1][0], sa[2 * kc + 1][1]);
            pf[3] = h2pack(sa[2 * kc + 1][2], sa[2 * kc + 1][3]);
            const int kk = kc * 16 + vkk;
#pragma unroll
            for (int d16 = 0; d16 < 4; d16++) {
                const int rr = d16 * 16 + vrr;
                const uint32_t addr = vb_ + rr * 128 + (((kk >> 3) ^ (rr & 7)) << 4);
                uint32_t vb4[4];
                LDSM4(vb4[0], vb4[1], vb4[2], vb4[3], addr);
                MMA_F16(oacc[2 * d16 + 0], pf, vb4);
                MMA_F16(oacc[2 * d16 + 1], pf, vb4 + 2);
            }
        }
        __syncthreads();
    }

    // ---- epilogue: normalize + store merged [B,L,D] ----
    const float inv0 = 1.0f / lr0;
    const float inv1 = 1.0f / lr1;
    const int b = bh >> 4, h = bh & 15;
    const int q0 = qb * 64 + w * 16 + (lane >> 2);
    float* o0 = g_o + ((size_t)(b * LL + q0)) * DM + h * 64 + 2 * (lane & 3);
    float* o1 = o0 + (size_t)8 * DM;
#pragma unroll
    for (int nt = 0; nt < 8; nt++) {
        float2 v0 = { oacc[nt][0] * inv0, oacc[nt][1] * inv0 };
        float2 v1 = { oacc[nt][2] * inv1, oacc[nt][3] * inv1 };
        *(float2*)(o0 + nt * 8) = v0;
        *(float2*)(o1 + nt * 8) = v1;
    }
#undef LOAD_TILE
}

// ---------------------------------------------------------------------------
// Launch
// ---------------------------------------------------------------------------
extern "C" void kernel_launch(void* const* d_in, const int* in_sizes, int n_in,
                              void* d_out, int out_size)
{
    const float* Q  = (const float*)d_in[0];
    const float* K  = (const float*)d_in[1];
    const float* V  = (const float*)d_in[2];
    const float* Wq = (const float*)d_in[4];
    const float* bq = (const float*)d_in[5];
    const float* Wk = (const float*)d_in[6];
    const float* bk = (const float*)d_in[7];
    const float* Wv = (const float*)d_in[8];
    const float* bv = (const float*)d_in[9];
    const float* Wo = (const float*)d_in[10];
    const float* bo = (const float*)d_in[11];
    float* out = (float*)d_out;

    float *gq, *gk, *go;
    __half* gvT;
    cudaGetSymbolAddress((void**)&gq, g_q);
    cudaGetSymbolAddress((void**)&gk, g_k);
    cudaGetSymbolAddress((void**)&gvT, g_vT);
    cudaGetSymbolAddress((void**)&go, g_o);

    cudaFuncSetAttribute(gemm_mma,
                         cudaFuncAttributeMaxDynamicSharedMemorySize, GEMM_SMEM);
    cudaFuncSetAttribute(attn_mma,
                         cudaFuncAttributeMaxDynamicSharedMemorySize, AT_SMEM);

    dim3 ggrid(DM / BN, MTOT / BM);   // (8, 32)

    gemm_mma<<<ggrid, 256, GEMM_SMEM>>>(Q, Wq, bq, gq, nullptr, 1);
    gemm_mma<<<ggrid, 256, GEMM_SMEM>>>(K, Wk, bk, gk, nullptr, 1);
    gemm_mma<<<ggrid, 256, GEMM_SMEM>>>(V, Wv, bv, nullptr, gvT, 2);

    attn_mma<<<dim3(LL / 64, BB * HH), 128, AT_SMEM>>>();

    gemm_mma<<<ggrid, 256, GEMM_SMEM>>>(go, Wo, bo, out, nullptr, 0);
}

// round 7
// speedup vs baseline: 15.0545x; 1.7674x over previous
#include <cuda_runtime.h>
#include <cuda_fp16.h>
#include <cstdint>
#include <math.h>

// Problem constants
#define BB   2
#define LL   2048
#define DM   1024
#define HH   16
#define MTOT (BB * LL)        // 4096

// f16 arena (element offsets)
#define OFF_XQ  (0u)
#define OFF_XK  (4u << 20)
#define OFF_XV  (8u << 20)
#define OFF_WQ  (12u << 20)
#define OFF_WK  (13u << 20)
#define OFF_WV  (14u << 20)
#define OFF_WO  (15u << 20)
#define OFF_QH  (16u << 20)   // head-split [B,H,L,64]
#define OFF_KH  (20u << 20)   // head-split [B,H,L,64]
#define OFF_VT  (24u << 20)   // transposed [B,H,64,L]
#define OFF_OH  (28u << 20)   // merged [B,L,D]
__device__ __align__(256) __half g_h[32u << 20];   // 64 MB

// ---------------------------------------------------------------------------
// helpers
// ---------------------------------------------------------------------------
__device__ __forceinline__ uint32_t smem_u32(const void* p) {
    uint32_t a;
    asm("{ .reg .u64 t; cvta.to.shared.u64 t, %1; cvt.u32.u64 %0, t; }"
        : "=r"(a) : "l"(p));
    return a;
}

#define LDSM4(r0, r1, r2, r3, addr)                                            \
    asm volatile("ldmatrix.sync.aligned.m8n8.x4.shared.b16 {%0,%1,%2,%3}, [%4];" \
                 : "=r"(r0), "=r"(r1), "=r"(r2), "=r"(r3) : "r"(addr))

#define MMA_F16(d, a, b)                                                       \
    asm volatile("mma.sync.aligned.m16n8k16.row.col.f32.f16.f16.f32 "          \
                 "{%0,%1,%2,%3},{%4,%5,%6,%7},{%8,%9},{%0,%1,%2,%3};"          \
                 : "+f"((d)[0]), "+f"((d)[1]), "+f"((d)[2]), "+f"((d)[3])      \
                 : "r"((a)[0]), "r"((a)[1]), "r"((a)[2]), "r"((a)[3]),         \
                   "r"((b)[0]), "r"((b)[1]))

#define CP_ASYNC16(dst, src) \
    asm volatile("cp.async.cg.shared.global [%0], [%1], 16;" :: "r"(dst), "l"(src) : "memory")
#define CP_COMMIT() asm volatile("cp.async.commit_group;" ::: "memory")
#define CP_WAIT(n)  asm volatile("cp.async.wait_group %0;" :: "n"(n) : "memory")

__device__ __forceinline__ uint32_t h2pack(float x, float y) {
    __half2 h = __floats2half2_rn(x, y);
    return *reinterpret_cast<uint32_t*>(&h);
}

// ---------------------------------------------------------------------------
// f32 -> f16 conversion (grid-stride, float4 -> half4)
// ---------------------------------------------------------------------------
__global__ void conv_h(const float4* __restrict__ src, uint2* __restrict__ dst, int n4)
{
    for (int i = blockIdx.x * blockDim.x + threadIdx.x; i < n4;
         i += gridDim.x * blockDim.x) {
        float4 v = src[i];
        uint2 r;
        r.x = h2pack(v.x, v.y);
        r.y = h2pack(v.z, v.w);
        dst[i] = r;
    }
}

// ---------------------------------------------------------------------------
// f16 mma.sync GEMM: out[m,n] = sum_k A[m,k]*W[n,k] + bias[n]
// BM=BN=128, BK=64; 256 threads (8 warps, 2x4, 64x32 warp tile).
// cp.async 3-stage pipeline; f16 operands; f32 accum.
// mode 0: f32 [m][n]; mode 1: f16 head-split [B,H,L,64];
// mode 2: f16 transposed [B,H,64,L]
// ---------------------------------------------------------------------------
#define GBK 64
#define GSTG 3
#define GST_BYTES (128 * 128)            // 16 KB per operand per stage
#define GEMM_SMEM (GSTG * 2 * GST_BYTES) // 98304 B
#define GNCH (DM / GBK)                  // 16

__global__ void __launch_bounds__(256, 2)
gemm_h(const __half* __restrict__ A, const __half* __restrict__ W,
       const float* __restrict__ bias, float* __restrict__ out,
       __half* __restrict__ outH, int mode)
{
    extern __shared__ char sm[];
    const uint32_t smA = smem_u32(sm);
    const uint32_t smB = smA + GSTG * GST_BYTES;

    const int tid  = threadIdx.x;
    const int lane = tid & 31;
    const int wid  = tid >> 5;
    const int wm   = (wid & 1) * 64;
    const int wn   = (wid >> 1) * 32;
    const int m0 = blockIdx.y * 128;
    const int n0 = blockIdx.x * 128;

#define GLOAD(c, s) do {                                                       \
    const int k0 = (c) * GBK;                                                  \
    _Pragma("unroll")                                                          \
    for (int j = 0; j < 4; j++) {                                              \
        const int i = tid + j * 256;                                           \
        const int row = i >> 3, c8 = i & 7;                                    \
        const uint32_t sw = row * 128 + ((c8 ^ (row & 7)) << 4);               \
        CP_ASYNC16(smA + (s) * GST_BYTES + sw,                                 \
                   A + (size_t)(m0 + row) * DM + k0 + c8 * 8);                 \
        CP_ASYNC16(smB + (s) * GST_BYTES + sw,                                 \
                   W + (size_t)(n0 + row) * DM + k0 + c8 * 8);                 \
    }                                                                          \
    CP_COMMIT();                                                               \
} while (0)

    float acc[4][4][4];
#pragma unroll
    for (int i = 0; i < 4; i++)
#pragma unroll
        for (int j = 0; j < 4; j++)
#pragma unroll
            for (int k = 0; k < 4; k++) acc[i][j][k] = 0.f;

    GLOAD(0, 0);
    GLOAD(1, 1);

    for (int c = 0; c < GNCH; ++c) {
        const int s = c % GSTG;
        if (c + 2 < GNCH) {
            GLOAD(c + 2, (c + 2) % GSTG);
            CP_WAIT(2);
        } else if (c + 1 < GNCH) {
            CP_WAIT(1);
        } else {
            CP_WAIT(0);
        }
        __syncthreads();

        const uint32_t aBase = smA + s * GST_BYTES;
        const uint32_t bBase = smB + s * GST_BYTES;
#pragma unroll
        for (int ks = 0; ks < 4; ks++) {
            uint32_t a[4][4], b[2][4];
#pragma unroll
            for (int mi = 0; mi < 4; mi++) {
                const int row = wm + mi * 16 + (lane & 15);
                const int kb = ks * 2 + (lane >> 4);
                const uint32_t addr = aBase + row * 128 + ((kb ^ (row & 7)) << 4);
                LDSM4(a[mi][0], a[mi][1], a[mi][2], a[mi][3], addr);
            }
#pragma unroll
            for (int nj = 0; nj < 2; nj++) {
                const int row = wn + nj * 16 + (lane & 7) + ((lane >> 4) & 1) * 8;
                const int kb = ks * 2 + ((lane >> 3) & 1);
                const uint32_t addr = bBase + row * 128 + ((kb ^ (row & 7)) << 4);
                LDSM4(b[nj][0], b[nj][1], b[nj][2], b[nj][3], addr);
            }
#pragma unroll
            for (int mi = 0; mi < 4; mi++) {
                MMA_F16(acc[mi][0], a[mi], b[0]);
                MMA_F16(acc[mi][1], a[mi], b[0] + 2);
                MMA_F16(acc[mi][2], a[mi], b[1]);
                MMA_F16(acc[mi][3], a[mi], b[1] + 2);
            }
        }
        __syncthreads();
    }

    const int r0q = lane >> 2;
    const int c0q = (lane & 3) * 2;
#pragma unroll
    for (int mi = 0; mi < 4; mi++) {
#pragma unroll
        for (int ni = 0; ni < 4; ni++) {
            const int n = n0 + wn + ni * 8 + c0q;
            const float2 b2 = *(const float2*)(bias + n);
#pragma unroll
            for (int h = 0; h < 2; h++) {
                const int m = m0 + wm + mi * 16 + r0q + h * 8;
                const float vx = acc[mi][ni][h * 2 + 0] + b2.x;
                const float vy = acc[mi][ni][h * 2 + 1] + b2.y;
                if (mode == 1) {
                    const int bb = m >> 11, l = m & 2047;
                    const int hh = n >> 6, d = n & 63;
                    __half2 hv = __floats2half2_rn(vx, vy);
                    *(__half2*)(outH + (((size_t)(bb * HH + hh) * LL + l) << 6) + d) = hv;
                } else if (mode == 2) {
                    const int bb = m >> 11, l = m & 2047;
                    const int hh = n >> 6, d = n & 63;
                    __half* p = outH + ((size_t)((bb * HH + hh) * 64 + d)) * LL + l;
                    p[0]  = __float2half_rn(vx);
                    p[LL] = __float2half_rn(vy);
                } else {
                    float2 v = { vx, vy };
                    *(float2*)(out + (size_t)m * DM + n) = v;
                }
            }
        }
    }
#undef GLOAD
}

// ---------------------------------------------------------------------------
// f16 tensor-core causal flash attention, d_k = 64.
// Grid: (L/64 [reversed], B*H). Block: 128 threads (4 warps).
// All operands f16 via cp.async; S and PV both m16n8k16; f32 softmax/accum.
// Output f16 merged [B,L,D].
// ---------------------------------------------------------------------------
#define AT_Q    0
#define AT_K    8192
#define AT_V    24576
#define AT_SMEM 40960

__global__ void __launch_bounds__(128)
attn_h()
{
    extern __shared__ char sm[];
    const uint32_t sbase = smem_u32(sm);
    const uint32_t sQ = sbase + AT_Q;
    const uint32_t sK = sbase + AT_K;
    const uint32_t sV = sbase + AT_V;

    const int tid = threadIdx.x;
    const int lane = tid & 31;
    const int w = tid >> 5;
    const int qb = (gridDim.x - 1) - blockIdx.x;   // heavy CTAs first
    const int bh = blockIdx.y;
    const size_t gb = (size_t)bh * LL * 64;
    const __half* qh  = g_h + OFF_QH + gb;
    const __half* kh  = g_h + OFF_KH + gb;
    const __half* vtg = g_h + OFF_VT + gb;

#define LOAD_TILE(kt, buf) do {                                                \
    _Pragma("unroll")                                                          \
    for (int j = 0; j < 4; j++) {                                              \
        const int i = tid + j * 128;                                           \
        const int r = i >> 3, c8 = i & 7;                                      \
        CP_ASYNC16(sK + (buf) * 8192 + r * 128 + ((c8 ^ (r & 7)) << 4),        \
                   kh + (size_t)((kt) * 64 + r) * 64 + c8 * 8);                \
    }                                                                          \
    _Pragma("unroll")                                                          \
    for (int j = 0; j < 4; j++) {                                              \
        const int i = tid + j * 128;                                           \
        const int d = i >> 3, c8 = i & 7;                                      \
        CP_ASYNC16(sV + (buf) * 8192 + d * 128 + ((c8 ^ (d & 7)) << 4),        \
                   vtg + (size_t)d * LL + (kt) * 64 + c8 * 8);                 \
    }                                                                          \
    CP_COMMIT();                                                               \
} while (0)

    // Q tile
#pragma unroll
    for (int j = 0; j < 4; j++) {
        const int i = tid + j * 128;
        const int r = i >> 3, c8 = i & 7;
        CP_ASYNC16(sQ + r * 128 + ((c8 ^ (r & 7)) << 4),
                   qh + (size_t)(qb * 64 + r) * 64 + c8 * 8);
    }
    CP_COMMIT();
    LOAD_TILE(0, 0);
    CP_WAIT(1);
    __syncthreads();

    // Q fragments (16 regs)
    uint32_t qf[4][4];
#pragma unroll
    for (int ks = 0; ks < 4; ks++) {
        const int row = w * 16 + (lane & 15);
        const int kb = ks * 2 + (lane >> 4);
        const uint32_t addr = sQ + row * 128 + ((kb ^ (row & 7)) << 4);
        LDSM4(qf[ks][0], qf[ks][1], qf[ks][2], qf[ks][3], addr);
    }

    float oacc[8][4];
#pragma unroll
    for (int i = 0; i < 8; i++)
#pragma unroll
        for (int j = 0; j < 4; j++) oacc[i][j] = 0.f;
    float mr0 = -1e30f, mr1 = -1e30f, lr0 = 0.f, lr1 = 0.f;

    const int qg0 = qb * 64 + w * 16 + (lane >> 2);
    const int qg1 = qg0 + 8;
    const int brr = (lane & 7) + ((lane >> 4) & 1) * 8;
    const int bkk = (lane >> 3) & 1;

    for (int kt = 0; kt <= qb; kt++) {
        const int s = kt & 1;
        if (kt < qb) {
            LOAD_TILE(kt + 1, s ^ 1);
            CP_WAIT(1);
        } else {
            CP_WAIT(0);
        }
        __syncthreads();

        // ---- S = Q K^T (f16) ----
        const uint32_t kb_ = sK + s * 8192;
        float sa[8][4];
#pragma unroll
        for (int i = 0; i < 8; i++)
#pragma unroll
            for (int j = 0; j < 4; j++) sa[i][j] = 0.f;
#pragma unroll
        for (int ks = 0; ks < 4; ks++) {
            const int kb = ks * 2 + bkk;
#pragma unroll
            for (int n16 = 0; n16 < 4; n16++) {
                const int rr = n16 * 16 + brr;
                const uint32_t addr = kb_ + rr * 128 + ((kb ^ (rr & 7)) << 4);
                uint32_t kb4[4];
                LDSM4(kb4[0], kb4[1], kb4[2], kb4[3], addr);
                MMA_F16(sa[2 * n16 + 0], qf[ks], kb4);
                MMA_F16(sa[2 * n16 + 1], qf[ks], kb4 + 2);
            }
        }

        // ---- mask + online softmax ----
        const bool diag = (kt == qb);
        const int colb = kt * 64 + 2 * (lane & 3);
        float tm0 = -1e30f, tm1 = -1e30f;
#pragma unroll
        for (int nt = 0; nt < 8; nt++) {
#pragma unroll
            for (int e = 0; e < 2; e++) {
                const int kg = colb + nt * 8 + e;
                float v0 = sa[nt][e] * 0.125f;
                if (diag && kg > qg0) v0 = -1e30f;
                sa[nt][e] = v0;
                tm0 = fmaxf(tm0, v0);
                float v1 = sa[nt][2 + e] * 0.125f;
                if (diag && kg > qg1) v1 = -1e30f;
                sa[nt][2 + e] = v1;
                tm1 = fmaxf(tm1, v1);
            }
        }
        tm0 = fmaxf(tm0, __shfl_xor_sync(0xffffffffu, tm0, 1));
        tm0 = fmaxf(tm0, __shfl_xor_sync(0xffffffffu, tm0, 2));
        tm1 = fmaxf(tm1, __shfl_xor_sync(0xffffffffu, tm1, 1));
        tm1 = fmaxf(tm1, __shfl_xor_sync(0xffffffffu, tm1, 2));

        const float mn0 = fmaxf(mr0, tm0);
        const float mn1 = fmaxf(mr1, tm1);
        const float corr0 = __expf(mr0 - mn0);
        const float corr1 = __expf(mr1 - mn1);
        float rs0 = 0.f, rs1 = 0.f;
#pragma unroll
        for (int nt = 0; nt < 8; nt++) {
#pragma unroll
            for (int e = 0; e < 2; e++) {
                const float p0 = __expf(sa[nt][e] - mn0);
                sa[nt][e] = p0; rs0 += p0;
                const float p1 = __expf(sa[nt][2 + e] - mn1);
                sa[nt][2 + e] = p1; rs1 += p1;
            }
        }
        rs0 += __shfl_xor_sync(0xffffffffu, rs0, 1);
        rs0 += __shfl_xor_sync(0xffffffffu, rs0, 2);
        rs1 += __shfl_xor_sync(0xffffffffu, rs1, 1);
        rs1 += __shfl_xor_sync(0xffffffffu, rs1, 2);
        lr0 = lr0 * corr0 + rs0;
        lr1 = lr1 * corr1 + rs1;
        mr0 = mn0; mr1 = mn1;
#pragma unroll
        for (int nt = 0; nt < 8; nt++) {
            oacc[nt][0] *= corr0; oacc[nt][1] *= corr0;
            oacc[nt][2] *= corr1; oacc[nt][3] *= corr1;
        }

        // ---- O += P V (f16) ----
        const uint32_t vb_ = sV + s * 8192;
#pragma unroll
        for (int kc = 0; kc < 4; kc++) {
            uint32_t pf[4];
            pf[0] = h2pack(sa[2 * kc][0],     sa[2 * kc][1]);
            pf[1] = h2pack(sa[2 * kc][2],     sa[2 * kc][3]);
            pf[2] = h2pack(sa[2 * kc + 1][0], sa[2 * kc + 1][1]);
            pf[3] = h2pack(sa[2 * kc + 1][2], sa[2 * kc + 1][3]);
            const int kb = kc * 2 + bkk;
#pragma unroll
            for (int d16 = 0; d16 < 4; d16++) {
                const int rr = d16 * 16 + brr;
                const uint32_t addr = vb_ + rr * 128 + ((kb ^ (rr & 7)) << 4);
                uint32_t vb4[4];
                LDSM4(vb4[0], vb4[1], vb4[2], vb4[3], addr);
                MMA_F16(oacc[2 * d16 + 0], pf, vb4);
                MMA_F16(oacc[2 * d16 + 1], pf, vb4 + 2);
            }
        }
        __syncthreads();
    }

    // ---- epilogue: normalize + f16 store merged [B,L,D] ----
    const float inv0 = 1.0f / lr0;
    const float inv1 = 1.0f / lr1;
    const int b = bh >> 4, h = bh & 15;
    const int q0 = qb * 64 + w * 16 + (lane >> 2);
    __half* o0 = g_h + OFF_OH + ((size_t)(b * LL + q0)) * DM + h * 64 + 2 * (lane & 3);
    __half* o1 = o0 + (size_t)8 * DM;
#pragma unroll
    for (int nt = 0; nt < 8; nt++) {
        *(__half2*)(o0 + nt * 8) = __floats2half2_rn(oacc[nt][0] * inv0, oacc[nt][1] * inv0);
        *(__half2*)(o1 + nt * 8) = __floats2half2_rn(oacc[nt][2] * inv1, oacc[nt][3] * inv1);
    }
#undef LOAD_TILE
}

// ---------------------------------------------------------------------------
// Launch
// ---------------------------------------------------------------------------
extern "C" void kernel_launch(void* const* d_in, const int* in_sizes, int n_in,
                              void* d_out, int out_size)
{
    const float* Q  = (const float*)d_in[0];
    const float* K  = (const float*)d_in[1];
    const float* V  = (const float*)d_in[2];
    const float* Wq = (const float*)d_in[4];
    const float* bq = (const float*)d_in[5];
    const float* Wk = (const float*)d_in[6];
    const float* bk = (const float*)d_in[7];
    const float* Wv = (const float*)d_in[8];
    const float* bv = (const float*)d_in[9];
    const float* Wo = (const float*)d_in[10];
    const float* bo = (const float*)d_in[11];
    float* out = (float*)d_out;

    __half* gh;
    cudaGetSymbolAddress((void**)&gh, g_h);

    cudaFuncSetAttribute(gemm_h,
                         cudaFuncAttributeMaxDynamicSharedMemorySize, GEMM_SMEM);
    cudaFuncSetAttribute(attn_h,
                         cudaFuncAttributeMaxDynamicSharedMemorySize, AT_SMEM);

    const int N4I = (MTOT * DM) / 4;   // inputs: 1M float4
    const int N4W = (DM * DM) / 4;     // weights: 256K float4

    conv_h<<<512, 256>>>((const float4*)Q,  (uint2*)(gh + OFF_XQ), N4I);
    conv_h<<<512, 256>>>((const float4*)K,  (uint2*)(gh + OFF_XK), N4I);
    conv_h<<<512, 256>>>((const float4*)V,  (uint2*)(gh + OFF_XV), N4I);
    conv_h<<<256, 256>>>((const float4*)Wq, (uint2*)(gh + OFF_WQ), N4W);
    conv_h<<<256, 256>>>((const float4*)Wk, (uint2*)(gh + OFF_WK), N4W);
    conv_h<<<256, 256>>>((const float4*)Wv, (uint2*)(gh + OFF_WV), N4W);
    conv_h<<<256, 256>>>((const float4*)Wo, (uint2*)(gh + OFF_WO), N4W);

    dim3 ggrid(DM / 128, MTOT / 128);   // (8, 32)

    gemm_h<<<ggrid, 256, GEMM_SMEM>>>(gh + OFF_XQ, gh + OFF_WQ, bq,
                                      nullptr, gh + OFF_QH, 1);
    gemm_h<<<ggrid, 256, GEMM_SMEM>>>(gh + OFF_XK, gh + OFF_WK, bk,
                                      nullptr, gh + OFF_KH, 1);
    gemm_h<<<ggrid, 256, GEMM_SMEM>>>(gh + OFF_XV, gh + OFF_WV, bv,
                                      nullptr, gh + OFF_VT, 2);

    attn_h<<<dim3(LL / 64, BB * HH), 128, AT_SMEM>>>();

    gemm_h<<<ggrid, 256, GEMM_SMEM>>>(gh + OFF_OH, gh + OFF_WO, bo,
                                      out, nullptr, 0);
}

// round 8
// speedup vs baseline: 16.6505x; 1.1060x over previous
#include <cuda_runtime.h>
#include <cuda_fp16.h>
#include <cstdint>
#include <math.h>

// Problem constants
#define BB   2
#define LL   2048
#define DM   1024
#define HH   16
#define MTOT (BB * LL)        // 4096

// f16 arena (element offsets)
#define OFF_XQ  (0u)
#define OFF_XK  (4u << 20)
#define OFF_XV  (8u << 20)
#define OFF_WQ  (12u << 20)
#define OFF_WK  (13u << 20)
#define OFF_WV  (14u << 20)
#define OFF_WO  (15u << 20)
#define OFF_QH  (16u << 20)   // head-split [B,H,L,64]
#define OFF_KH  (20u << 20)   // head-split [B,H,L,64]
#define OFF_VT  (24u << 20)   // transposed [B,H,64,L]
#define OFF_OH  (28u << 20)   // merged [B,L,D]
__device__ __align__(256) __half g_h[32u << 20];   // 64 MB

// ---------------------------------------------------------------------------
// helpers
// ---------------------------------------------------------------------------
__device__ __forceinline__ uint32_t smem_u32(const void* p) {
    uint32_t a;
    asm("{ .reg .u64 t; cvta.to.shared.u64 t, %1; cvt.u32.u64 %0, t; }"
        : "=r"(a) : "l"(p));
    return a;
}

#define LDSM4(r0, r1, r2, r3, addr)                                            \
    asm volatile("ldmatrix.sync.aligned.m8n8.x4.shared.b16 {%0,%1,%2,%3}, [%4];" \
                 : "=r"(r0), "=r"(r1), "=r"(r2), "=r"(r3) : "r"(addr))

#define MMA_F16(d, a, b)                                                       \
    asm volatile("mma.sync.aligned.m16n8k16.row.col.f32.f16.f16.f32 "          \
                 "{%0,%1,%2,%3},{%4,%5,%6,%7},{%8,%9},{%0,%1,%2,%3};"          \
                 : "+f"((d)[0]), "+f"((d)[1]), "+f"((d)[2]), "+f"((d)[3])      \
                 : "r"((a)[0]), "r"((a)[1]), "r"((a)[2]), "r"((a)[3]),         \
                   "r"((b)[0]), "r"((b)[1]))

#define CP_ASYNC16(dst, src) \
    asm volatile("cp.async.cg.shared.global [%0], [%1], 16;" :: "r"(dst), "l"(src) : "memory")
#define CP_COMMIT() asm volatile("cp.async.commit_group;" ::: "memory")
#define CP_WAIT(n)  asm volatile("cp.async.wait_group %0;" :: "n"(n) : "memory")

__device__ __forceinline__ uint32_t h2pack(float x, float y) {
    __half2 h = __floats2half2_rn(x, y);
    return *reinterpret_cast<uint32_t*>(&h);
}

// ---------------------------------------------------------------------------
// Fused f32 -> f16 conversion for all 7 tensors (one launch)
// Segments (float4 units): 3 inputs x 1M, 4 weights x 256K.
// ---------------------------------------------------------------------------
#define N4I ((MTOT * DM) / 4)   // 1048576
#define N4W ((DM * DM) / 4)     // 262144

struct CArgs {
    const float4* src[7];
    uint2* dst[7];
};

__global__ void __launch_bounds__(256)
conv_all(CArgs a)
{
    const int total = 3 * N4I + 4 * N4W;
    for (int i = blockIdx.x * blockDim.x + threadIdx.x; i < total;
         i += gridDim.x * blockDim.x) {
        int seg, off;
        if (i < 3 * N4I) { seg = i / N4I; off = i - seg * N4I; }
        else { const int j = i - 3 * N4I; seg = 3 + (j >> 18); off = j & (N4W - 1); }
        const float4 v = a.src[seg][off];
        uint2 r;
        r.x = h2pack(v.x, v.y);
        r.y = h2pack(v.z, v.w);
        a.dst[seg][off] = r;
    }
}

// ---------------------------------------------------------------------------
// f16 mma.sync GEMM core (shared by QKV-fused and O-proj kernels).
// BM=BN=128, BK=64; 256 threads (8 warps, 2x4, 64x32 warp tile).
// cp.async 3-stage pipeline; f16 operands; f32 accum.
// ---------------------------------------------------------------------------
#define GBK 64
#define GSTG 3
#define GST_BYTES (128 * 128)            // 16 KB per operand per stage
#define GEMM_SMEM (GSTG * 2 * GST_BYTES) // 98304 B
#define GNCH (DM / GBK)                  // 16

struct GemmFrag {
    float acc[4][4][4];
    int lane, wm, wn;
};

__device__ __forceinline__ void gemm_core(
    const __half* __restrict__ A, const __half* __restrict__ W,
    uint32_t smA, uint32_t smB, int m0, int n0, int tid, GemmFrag& G)
{
    const int lane = tid & 31;
    const int wid  = tid >> 5;
    G.lane = lane;
    G.wm = (wid & 1) * 64;
    G.wn = (wid >> 1) * 32;

#define GLOAD(c, s) do {                                                       \
    const int k0 = (c) * GBK;                                                  \
    _Pragma("unroll")                                                          \
    for (int j = 0; j < 4; j++) {                                              \
        const int i = tid + j * 256;                                           \
        const int row = i >> 3, c8 = i & 7;                                    \
        const uint32_t sw = row * 128 + ((c8 ^ (row & 7)) << 4);               \
        CP_ASYNC16(smA + (s) * GST_BYTES + sw,                                 \
                   A + (size_t)(m0 + row) * DM + k0 + c8 * 8);                 \
        CP_ASYNC16(smB + (s) * GST_BYTES + sw,                                 \
                   W + (size_t)(n0 + row) * DM + k0 + c8 * 8);                 \
    }                                                                          \
    CP_COMMIT();                                                               \
} while (0)

#pragma unroll
    for (int i = 0; i < 4; i++)
#pragma unroll
        for (int j = 0; j < 4; j++)
#pragma unroll
            for (int k = 0; k < 4; k++) G.acc[i][j][k] = 0.f;

    GLOAD(0, 0);
    GLOAD(1, 1);

    for (int c = 0; c < GNCH; ++c) {
        const int s = c % GSTG;
        if (c + 2 < GNCH) {
            GLOAD(c + 2, (c + 2) % GSTG);
            CP_WAIT(2);
        } else if (c + 1 < GNCH) {
            CP_WAIT(1);
        } else {
            CP_WAIT(0);
        }
        __syncthreads();

        const uint32_t aBase = smA + s * GST_BYTES;
        const uint32_t bBase = smB + s * GST_BYTES;
#pragma unroll
        for (int ks = 0; ks < 4; ks++) {
            uint32_t a[4][4], b[2][4];
#pragma unroll
            for (int mi = 0; mi < 4; mi++) {
                const int row = G.wm + mi * 16 + (lane & 15);
                const int kb = ks * 2 + (lane >> 4);
                const uint32_t addr = aBase + row * 128 + ((kb ^ (row & 7)) << 4);
                LDSM4(a[mi][0], a[mi][1], a[mi][2], a[mi][3], addr);
            }
#pragma unroll
            for (int nj = 0; nj < 2; nj++) {
                const int row = G.wn + nj * 16 + (lane & 7) + ((lane >> 4) & 1) * 8;
                const int kb = ks * 2 + ((lane >> 3) & 1);
                const uint32_t addr = bBase + row * 128 + ((kb ^ (row & 7)) << 4);
                LDSM4(b[nj][0], b[nj][1], b[nj][2], b[nj][3], addr);
            }
#pragma unroll
            for (int mi = 0; mi < 4; mi++) {
                MMA_F16(G.acc[mi][0], a[mi], b[0]);
                MMA_F16(G.acc[mi][1], a[mi], b[0] + 2);
                MMA_F16(G.acc[mi][2], a[mi], b[1]);
                MMA_F16(G.acc[mi][3], a[mi], b[1] + 2);
            }
        }
        __syncthreads();
    }
#undef GLOAD
}

// ---------------------------------------------------------------------------
// Fused Q/K/V projection GEMMs: blockIdx.z selects projection.
// z=0: Q -> f16 head-split; z=1: K -> f16 head-split; z=2: V -> f16 transposed.
// ---------------------------------------------------------------------------
__global__ void __launch_bounds__(256, 2)
gemm_qkv(const float* __restrict__ bq, const float* __restrict__ bk,
         const float* __restrict__ bv)
{
    extern __shared__ char sm[];
    const uint32_t smA = smem_u32(sm);
    const uint32_t smB = smA + GSTG * GST_BYTES;
    const int tid = threadIdx.x;
    const int z = blockIdx.z;
    const int m0 = blockIdx.y * 128;
    const int n0 = blockIdx.x * 128;

    const __half* A = g_h + (z == 0 ? OFF_XQ : z == 1 ? OFF_XK : OFF_XV);
    const __half* W = g_h + OFF_WQ + ((uint32_t)z << 20);
    const float* bias = (z == 0 ? bq : z == 1 ? bk : bv);
    __half* outH = g_h + (z == 0 ? OFF_QH : z == 1 ? OFF_KH : OFF_VT);

    GemmFrag G;
    gemm_core(A, W, smA, smB, m0, n0, tid, G);

    const int lane = G.lane;
    const int r0q = lane >> 2;
    const int c0q = (lane & 3) * 2;
#pragma unroll
    for (int mi = 0; mi < 4; mi++) {
#pragma unroll
        for (int ni = 0; ni < 4; ni++) {
            const int n = n0 + G.wn + ni * 8 + c0q;
            const float2 b2 = *(const float2*)(bias + n);
#pragma unroll
            for (int h = 0; h < 2; h++) {
                const int m = m0 + G.wm + mi * 16 + r0q + h * 8;
                const float vx = G.acc[mi][ni][h * 2 + 0] + b2.x;
                const float vy = G.acc[mi][ni][h * 2 + 1] + b2.y;
                const int bb = m >> 11, l = m & 2047;
                const int hh = n >> 6, d = n & 63;
                if (z != 2) {
                    __half2 hv = __floats2half2_rn(vx, vy);
                    *(__half2*)(outH + (((size_t)(bb * HH + hh) * LL + l) << 6) + d) = hv;
                } else {
                    __half* p = outH + ((size_t)((bb * HH + hh) * 64 + d)) * LL + l;
                    p[0]  = __float2half_rn(vx);
                    p[LL] = __float2half_rn(vy);
                }
            }
        }
    }
}

// ---------------------------------------------------------------------------
// Output projection GEMM: f16 in, f32 out.
// ---------------------------------------------------------------------------
__global__ void __launch_bounds__(256, 2)
gemm_o(const float* __restrict__ bias, float* __restrict__ out)
{
    extern __shared__ char sm[];
    const uint32_t smA = smem_u32(sm);
    const uint32_t smB = smA + GSTG * GST_BYTES;
    const int tid = threadIdx.x;
    const int m0 = blockIdx.y * 128;
    const int n0 = blockIdx.x * 128;

    GemmFrag G;
    gemm_core(g_h + OFF_OH, g_h + OFF_WO, smA, smB, m0, n0, tid, G);

    const int lane = G.lane;
    const int r0q = lane >> 2;
    const int c0q = (lane & 3) * 2;
#pragma unroll
    for (int mi = 0; mi < 4; mi++) {
#pragma unroll
        for (int ni = 0; ni < 4; ni++) {
            const int n = n0 + G.wn + ni * 8 + c0q;
            const float2 b2 = *(const float2*)(bias + n);
#pragma unroll
            for (int h = 0; h < 2; h++) {
                const int m = m0 + G.wm + mi * 16 + r0q + h * 8;
                float2 v;
                v.x = G.acc[mi][ni][h * 2 + 0] + b2.x;
                v.y = G.acc[mi][ni][h * 2 + 1] + b2.y;
                *(float2*)(out + (size_t)m * DM + n) = v;
            }
        }
    }
}

// ---------------------------------------------------------------------------
// f16 tensor-core causal flash attention, d_k = 64.
// Grid: (L/64 [reversed], B*H). Block: 128 threads (4 warps).
// exp2-based softmax (scale folded with log2e). Output f16 merged [B,L,D].
// ---------------------------------------------------------------------------
#define AT_Q    0
#define AT_K    8192
#define AT_V    24576
#define AT_SMEM 40960
#define SCL 0.18033688f   // 0.125 * log2(e)

__global__ void __launch_bounds__(128)
attn_h()
{
    extern __shared__ char sm[];
    const uint32_t sbase = smem_u32(sm);
    const uint32_t sQ = sbase + AT_Q;
    const uint32_t sK = sbase + AT_K;
    const uint32_t sV = sbase + AT_V;

    const int tid = threadIdx.x;
    const int lane = tid & 31;
    const int w = tid >> 5;
    const int qb = (gridDim.x - 1) - blockIdx.x;   // heavy CTAs first
    const int bh = blockIdx.y;
    const size_t gb = (size_t)bh * LL * 64;
    const __half* qh  = g_h + OFF_QH + gb;
    const __half* kh  = g_h + OFF_KH + gb;
    const __half* vtg = g_h + OFF_VT + gb;

#define LOAD_TILE(kt, buf) do {                                                \
    _Pragma("unroll")                                                          \
    for (int j = 0; j < 4; j++) {                                              \
        const int i = tid + j * 128;                                           \
        const int r = i >> 3, c8 = i & 7;                                      \
        CP_ASYNC16(sK + (buf) * 8192 + r * 128 + ((c8 ^ (r & 7)) << 4),        \
                   kh + (size_t)((kt) * 64 + r) * 64 + c8 * 8);                \
    }                                                                          \
    _Pragma("unroll")                                                          \
    for (int j = 0; j < 4; j++) {                                              \
        const int i = tid + j * 128;                                           \
        const int d = i >> 3, c8 = i & 7;                                      \
        CP_ASYNC16(sV + (buf) * 8192 + d * 128 + ((c8 ^ (d & 7)) << 4),        \
                   vtg + (size_t)d * LL + (kt) * 64 + c8 * 8);                 \
    }                                                                          \
    CP_COMMIT();                                                               \
} while (0)

    // Q tile
#pragma unroll
    for (int j = 0; j < 4; j++) {
        const int i = tid + j * 128;
        const int r = i >> 3, c8 = i & 7;
        CP_ASYNC16(sQ + r * 128 + ((c8 ^ (r & 7)) << 4),
                   qh + (size_t)(qb * 64 + r) * 64 + c8 * 8);
    }
    CP_COMMIT();
    LOAD_TILE(0, 0);
    CP_WAIT(1);
    __syncthreads();

    // Q fragments (16 regs)
    uint32_t qf[4][4];
#pragma unroll
    for (int ks = 0; ks < 4; ks++) {
        const int row = w * 16 + (lane & 15);
        const int kb = ks * 2 + (lane >> 4);
        const uint32_t addr = sQ + row * 128 + ((kb ^ (row & 7)) << 4);
        LDSM4(qf[ks][0], qf[ks][1], qf[ks][2], qf[ks][3], addr);
    }

    float oacc[8][4];
#pragma unroll
    for (int i = 0; i < 8; i++)
#pragma unroll
        for (int j = 0; j < 4; j++) oacc[i][j] = 0.f;
    float mr0 = -1e30f, mr1 = -1e30f, lr0 = 0.f, lr1 = 0.f;

    const int qg0 = qb * 64 + w * 16 + (lane >> 2);
    const int qg1 = qg0 + 8;
    const int brr = (lane & 7) + ((lane >> 4) & 1) * 8;
    const int bkk = (lane >> 3) & 1;

    for (int kt = 0; kt <= qb; kt++) {
        const int s = kt & 1;
        if (kt < qb) {
            LOAD_TILE(kt + 1, s ^ 1);
            CP_WAIT(1);
        } else {
            CP_WAIT(0);
        }
        __syncthreads();

        // ---- S = Q K^T (f16) ----
        const uint32_t kb_ = sK + s * 8192;
        float sa[8][4];
#pragma unroll
        for (int i = 0; i < 8; i++)
#pragma unroll
            for (int j = 0; j < 4; j++) sa[i][j] = 0.f;
#pragma unroll
        for (int ks = 0; ks < 4; ks++) {
            const int kb = ks * 2 + bkk;
#pragma unroll
            for (int n16 = 0; n16 < 4; n16++) {
                const int rr = n16 * 16 + brr;
                const uint32_t addr = kb_ + rr * 128 + ((kb ^ (rr & 7)) << 4);
                uint32_t kb4[4];
                LDSM4(kb4[0], kb4[1], kb4[2], kb4[3], addr);
                MMA_F16(sa[2 * n16 + 0], qf[ks], kb4);
                MMA_F16(sa[2 * n16 + 1], qf[ks], kb4 + 2);
            }
        }

        // ---- mask + online softmax (base-2) ----
        const bool diag = (kt == qb);
        const int colb = kt * 64 + 2 * (lane & 3);
        float tm0 = -1e30f, tm1 = -1e30f;
#pragma unroll
        for (int nt = 0; nt < 8; nt++) {
#pragma unroll
            for (int e = 0; e < 2; e++) {
                const int kg = colb + nt * 8 + e;
                float v0 = sa[nt][e] * SCL;
                if (diag && kg > qg0) v0 = -1e30f;
                sa[nt][e] = v0;
                tm0 = fmaxf(tm0, v0);
                float v1 = sa[nt][2 + e] * SCL;
                if (diag && kg > qg1) v1 = -1e30f;
                sa[nt][2 + e] = v1;
                tm1 = fmaxf(tm1, v1);
            }
        }
        tm0 = fmaxf(tm0, __shfl_xor_sync(0xffffffffu, tm0, 1));
        tm0 = fmaxf(tm0, __shfl_xor_sync(0xffffffffu, tm0, 2));
        tm1 = fmaxf(tm1, __shfl_xor_sync(0xffffffffu, tm1, 1));
        tm1 = fmaxf(tm1, __shfl_xor_sync(0xffffffffu, tm1, 2));

        const float mn0 = fmaxf(mr0, tm0);
        const float mn1 = fmaxf(mr1, tm1);
        const float corr0 = exp2f(mr0 - mn0);
        const float corr1 = exp2f(mr1 - mn1);
        float rs0 = 0.f, rs1 = 0.f;
#pragma unroll
        for (int nt = 0; nt < 8; nt++) {
#pragma unroll
            for (int e = 0; e < 2; e++) {
                const float p0 = exp2f(sa[nt][e] - mn0);
                sa[nt][e] = p0; rs0 += p0;
                const float p1 = exp2f(sa[nt][2 + e] - mn1);
                sa[nt][2 + e] = p1; rs1 += p1;
            }
        }
        rs0 += __shfl_xor_sync(0xffffffffu, rs0, 1);
        rs0 += __shfl_xor_sync(0xffffffffu, rs0, 2);
        rs1 += __shfl_xor_sync(0xffffffffu, rs1, 1);
        rs1 += __shfl_xor_sync(0xffffffffu, rs1, 2);
        lr0 = lr0 * corr0 + rs0;
        lr1 = lr1 * corr1 + rs1;
        mr0 = mn0; mr1 = mn1;
#pragma unroll
        for (int nt = 0; nt < 8; nt++) {
            oacc[nt][0] *= corr0; oacc[nt][1] *= corr0;
            oacc[nt][2] *= corr1; oacc[nt][3] *= corr1;
        }

        // ---- O += P V (f16) ----
        const uint32_t vb_ = sV + s * 8192;
#pragma unroll
        for (int kc = 0; kc < 4; kc++) {
            uint32_t pf[4];
            pf[0] = h2pack(sa[2 * kc][0],     sa[2 * kc][1]);
            pf[1] = h2pack(sa[2 * kc][2],     sa[2 * kc][3]);
            pf[2] = h2pack(sa[2 * kc + 1][0], sa[2 * kc + 1][1]);
            pf[3] = h2pack(sa[2 * kc + 1][2], sa[2 * kc + 1][3]);
            const int kb = kc * 2 + bkk;
#pragma unroll
            for (int d16 = 0; d16 < 4; d16++) {
                const int rr = d16 * 16 + brr;
                const uint32_t addr = vb_ + rr * 128 + ((kb ^ (rr & 7)) << 4);
                uint32_t vb4[4];
                LDSM4(vb4[0], vb4[1], vb4[2], vb4[3], addr);
                MMA_F16(oacc[2 * d16 + 0], pf, vb4);
                MMA_F16(oacc[2 * d16 + 1], pf, vb4 + 2);
            }
        }
        __syncthreads();
    }

    // ---- epilogue: normalize + f16 store merged [B,L,D] ----
    const float inv0 = 1.0f / lr0;
    const float inv1 = 1.0f / lr1;
    const int b = bh >> 4, h = bh & 15;
    const int q0 = qb * 64 + w * 16 + (lane >> 2);
    __half* o0 = g_h + OFF_OH + ((size_t)(b * LL + q0)) * DM + h * 64 + 2 * (lane & 3);
    __half* o1 = o0 + (size_t)8 * DM;
#pragma unroll
    for (int nt = 0; nt < 8; nt++) {
        *(__half2*)(o0 + nt * 8) = __floats2half2_rn(oacc[nt][0] * inv0, oacc[nt][1] * inv0);
        *(__half2*)(o1 + nt * 8) = __floats2half2_rn(oacc[nt][2] * inv1, oacc[nt][3] * inv1);
    }
#undef LOAD_TILE
}

// ---------------------------------------------------------------------------
// Launch
// ---------------------------------------------------------------------------
extern "C" void kernel_launch(void* const* d_in, const int* in_sizes, int n_in,
                              void* d_out, int out_size)
{
    const float* Q  = (const float*)d_in[0];
    const float* K  = (const float*)d_in[1];
    const float* V  = (const float*)d_in[2];
    const float* Wq = (const float*)d_in[4];
    const float* bq = (const float*)d_in[5];
    const float* Wk = (const float*)d_in[6];
    const float* bk = (const float*)d_in[7];
    const float* Wv = (const float*)d_in[8];
    const float* bv = (const float*)d_in[9];
    const float* Wo = (const float*)d_in[10];
    const float* bo = (const float*)d_in[11];
    float* out = (float*)d_out;

    __half* gh;
    cudaGetSymbolAddress((void**)&gh, g_h);

    cudaFuncSetAttribute(gemm_qkv,
                         cudaFuncAttributeMaxDynamicSharedMemorySize, GEMM_SMEM);
    cudaFuncSetAttribute(gemm_o,
                         cudaFuncAttributeMaxDynamicSharedMemorySize, GEMM_SMEM);
    cudaFuncSetAttribute(attn_h,
                         cudaFuncAttributeMaxDynamicSharedMemorySize, AT_SMEM);

    CArgs ca;
    ca.src[0] = (const float4*)Q;  ca.dst[0] = (uint2*)(gh + OFF_XQ);
    ca.src[1] = (const float4*)K;  ca.dst[1] = (uint2*)(gh + OFF_XK);
    ca.src[2] = (const float4*)V;  ca.dst[2] = (uint2*)(gh + OFF_XV);
    ca.src[3] = (const float4*)Wq; ca.dst[3] = (uint2*)(gh + OFF_WQ);
    ca.src[4] = (const float4*)Wk; ca.dst[4] = (uint2*)(gh + OFF_WK);
    ca.src[5] = (const float4*)Wv; ca.dst[5] = (uint2*)(gh + OFF_WV);
    ca.src[6] = (const float4*)Wo; ca.dst[6] = (uint2*)(gh + OFF_WO);
    conv_all<<<1184, 256>>>(ca);

    gemm_qkv<<<dim3(DM / 128, MTOT / 128, 3), 256, GEMM_SMEM>>>(bq, bk, bv);

    attn_h<<<dim3(LL / 64, BB * HH), 128, AT_SMEM>>>();

    gemm_o<<<dim3(DM / 128, MTOT / 128), 256, GEMM_SMEM>>>(bo, out);
}